// round 9
// baseline (speedup 1.0000x reference)
#include <cuda_runtime.h>
#include <cstdint>
#include <cstddef>

// ---------------------------------------------------------------------------
// AudioMamba forward on GB300 — R9: 64x128-tile GEMM cores, >=256-block grids
// for 2+ CTAs/SM. Elementwise structure identical to R7 (best known).
// ---------------------------------------------------------------------------

constexpr int NS = 16;
constexpr int XDW = 64;

// ---- scratch --------------------------------------------------------------
constexpr size_t OFF_H    = 0;
constexpr size_t OFF_XN   = OFF_H    + 1024 * 512;
constexpr size_t OFF_XZ   = OFF_XN   + 1024 * 512;
constexpr size_t OFF_U0   = OFF_XZ   + 1024 * 2048;
constexpr size_t OFF_XD0  = OFF_U0   + 2 * 1024 * 1024;
constexpr size_t OFF_Y0   = OFF_XD0  + 2 * 1024 * XDW;
constexpr size_t OFF_YG   = OFF_Y0   + 2 * 1024 * 1024;
constexpr size_t OFF_IM   = OFF_YG   + 1024 * 1024;
constexpr size_t OFF_XPP  = OFF_IM   + 1024 * 256;        // 32 x 1024 x 64
constexpr size_t OFF_OPP  = OFF_XPP  + 32 * 1024 * 64;    // 4 x 1024 x 512
constexpr size_t OFF_FEAT = OFF_OPP  + 4 * 1024 * 512;
constexpr size_t OFF_C    = OFF_FEAT + 4 * 512;
constexpr size_t OFF_F1   = OFF_C    + 4 * 512;
constexpr size_t SCRATCH_FLOATS = OFF_F1 + 4 * 512;

__device__ __align__(16) float g_scratch[SCRATCH_FLOATS];

// ---------------------------------------------------------------------------
// tf32 helpers
// ---------------------------------------------------------------------------
__device__ __forceinline__ float f2tf32(float f) {
    uint32_t u;
    asm("cvt.rna.tf32.f32 %0, %1;" : "=r"(u) : "f"(f));
    return __uint_as_float(u);
}
__device__ __forceinline__ float4 cvt4(float4 v) {
    return make_float4(f2tf32(v.x), f2tf32(v.y), f2tf32(v.z), f2tf32(v.w));
}

__device__ __forceinline__ void mma_tf32(float& c0, float& c1, float& c2, float& c3,
                                         uint32_t a0, uint32_t a1, uint32_t a2, uint32_t a3,
                                         uint32_t b0, uint32_t b1)
{
    asm volatile(
        "mma.sync.aligned.m16n8k8.row.col.f32.tf32.tf32.f32 "
        "{%0,%1,%2,%3}, {%4,%5,%6,%7}, {%8,%9}, {%0,%1,%2,%3};\n"
        : "+f"(c0), "+f"(c1), "+f"(c2), "+f"(c3)
        : "r"(a0), "r"(a1), "r"(a2), "r"(a3), "r"(b0), "r"(b1));
}

// ===========================================================================
// 64x128 core: 64 rows x 128 cols, BK=16, 256 threads, 8 warps of 32x32.
// wy = warp>>2 (0..1) -> rows wy*32; wx = warp&3 -> cols wx*32.
// acc[mf 0..1][nt 0..3][4]. Frag: c0(r,c) c1(r,c+1) c2(r+8,c) c3(r+8,c+1),
//   r = wy*32+mf*16+lane/4, c = wx*32+nt*8+2*(lane%4).
// ===========================================================================
__device__ __forceinline__ void mma_core_64x128(const float* __restrict__ Ab, int lda,
                                                const float* __restrict__ Wb, int ldw,
                                                int kend, float (&acc)[2][4][4])
{
    __shared__ __align__(16) float As[2][64][20];
    __shared__ __align__(16) float Bs[2][128][20];

    const int tid  = threadIdx.x;
    const int warp = tid >> 5, lane = tid & 31;
    const int wy = warp >> 2, wx = warp & 3;
    const int g = lane >> 2, t = lane & 3;

    const int arow = tid >> 2, acol = (tid & 3) * 4;   // 4 thr/row, 4 floats
    const int brow = tid >> 1, bcol = (tid & 1) * 8;   // 2 thr/row, 8 floats

    {
        float4 va = *reinterpret_cast<const float4*>(Ab + (size_t)arow * lda + acol);
        float4 b0 = *reinterpret_cast<const float4*>(Wb + (size_t)brow * ldw + bcol);
        float4 b1 = *reinterpret_cast<const float4*>(Wb + (size_t)brow * ldw + bcol + 4);
        *reinterpret_cast<float4*>(&As[0][arow][acol])     = cvt4(va);
        *reinterpret_cast<float4*>(&Bs[0][brow][bcol])     = cvt4(b0);
        *reinterpret_cast<float4*>(&Bs[0][brow][bcol + 4]) = cvt4(b1);
    }
    __syncthreads();

    const int niter = kend >> 4;
    for (int it = 0; it < niter; it++) {
        const int cur = it & 1;
        float4 pa, pb0, pb1;
        const bool more = (it + 1 < niter);
        if (more) {
            int k0 = (it + 1) << 4;
            pa  = *reinterpret_cast<const float4*>(Ab + (size_t)arow * lda + k0 + acol);
            pb0 = *reinterpret_cast<const float4*>(Wb + (size_t)brow * ldw + k0 + bcol);
            pb1 = *reinterpret_cast<const float4*>(Wb + (size_t)brow * ldw + k0 + bcol + 4);
        }

#pragma unroll
        for (int k8 = 0; k8 < 16; k8 += 8) {
            uint32_t a[2][4], b[4][2];
#pragma unroll
            for (int mf = 0; mf < 2; mf++) {
                const int ar = wy * 32 + mf * 16 + g;
                a[mf][0] = __float_as_uint(As[cur][ar][k8 + t]);
                a[mf][1] = __float_as_uint(As[cur][ar + 8][k8 + t]);
                a[mf][2] = __float_as_uint(As[cur][ar][k8 + t + 4]);
                a[mf][3] = __float_as_uint(As[cur][ar + 8][k8 + t + 4]);
            }
#pragma unroll
            for (int nt = 0; nt < 4; nt++) {
                const int bn = wx * 32 + nt * 8 + g;
                b[nt][0] = __float_as_uint(Bs[cur][bn][k8 + t]);
                b[nt][1] = __float_as_uint(Bs[cur][bn][k8 + t + 4]);
            }
#pragma unroll
            for (int mf = 0; mf < 2; mf++)
#pragma unroll
                for (int nt = 0; nt < 4; nt++)
                    mma_tf32(acc[mf][nt][0], acc[mf][nt][1], acc[mf][nt][2], acc[mf][nt][3],
                             a[mf][0], a[mf][1], a[mf][2], a[mf][3],
                             b[nt][0], b[nt][1]);
        }

        if (more) {
            const int nxt = cur ^ 1;
            *reinterpret_cast<float4*>(&As[nxt][arow][acol])     = cvt4(pa);
            *reinterpret_cast<float4*>(&Bs[nxt][brow][bcol])     = cvt4(pb0);
            *reinterpret_cast<float4*>(&Bs[nxt][brow][bcol + 4]) = cvt4(pb1);
            __syncthreads();
        }
    }
}

#define P64_PROLOGUE                                              \
    const int warp = threadIdx.x >> 5, lane = threadIdx.x & 31;   \
    const int wy = warp >> 2, wx = warp & 3;                      \
    const int g = lane >> 2, t = lane & 3;                        \
    float acc[2][4][4];                                           \
    _Pragma("unroll")                                             \
    for (int i = 0; i < 2; i++)                                   \
        _Pragma("unroll")                                         \
        for (int j = 0; j < 4; j++)                               \
            _Pragma("unroll")                                     \
            for (int q = 0; q < 4; q++) acc[i][j][q] = 0.f;

// in_proj: C[1024,2048] = A[1024,512]*W^T. grid (16, 16) = 256 blocks.
__global__ void __launch_bounds__(256)
gemm64_inproj(const float* __restrict__ A,
              const float* __restrict__ W,
              float* __restrict__ C)
{
    const int rowBase = blockIdx.y * 64;
    const int colBase = blockIdx.x * 128;
    P64_PROLOGUE
    mma_core_64x128(A + (size_t)rowBase * 512, 512, W + (size_t)colBase * 512, 512, 512, acc);

#pragma unroll
    for (int mf = 0; mf < 2; mf++) {
        const int r0 = rowBase + wy * 32 + mf * 16 + g;
#pragma unroll
        for (int nt = 0; nt < 4; nt++) {
            int cb = colBase + wx * 32 + nt * 8 + 2 * t;
            *reinterpret_cast<float2*>(&C[(size_t)r0 * 2048 + cb])       = make_float2(acc[mf][nt][0], acc[mf][nt][1]);
            *reinterpret_cast<float2*>(&C[(size_t)(r0 + 8) * 2048 + cb]) = make_float2(acc[mf][nt][2], acc[mf][nt][3]);
        }
    }
}

// out_proj partial, split-K(4): grid (4 n, 16 m, 4 kc) = 256 blocks. K-chunk 256.
__global__ void __launch_bounds__(256)
gemm64_op_part(const float* __restrict__ yg, const float* __restrict__ Wop,
               float* __restrict__ partial)
{
    const int kc = blockIdx.z;
    const float* A = yg + kc * 256;
    const float* W = Wop + kc * 256;
    const int rowBase = blockIdx.y * 64;
    const int colBase = blockIdx.x * 128;
    P64_PROLOGUE
    mma_core_64x128(A + (size_t)rowBase * 1024, 1024, W + (size_t)colBase * 1024, 1024, 256, acc);

    float* out = partial + (size_t)kc * (1024 * 512);
#pragma unroll
    for (int mf = 0; mf < 2; mf++) {
        const int r0 = rowBase + wy * 32 + mf * 16 + g;
#pragma unroll
        for (int nt = 0; nt < 4; nt++) {
            int cb = colBase + wx * 32 + nt * 8 + 2 * t;
            *reinterpret_cast<float2*>(&out[(size_t)r0 * 512 + cb])       = make_float2(acc[mf][nt][0], acc[mf][nt][1]);
            *reinterpret_cast<float2*>(&out[(size_t)(r0 + 8) * 512 + cb]) = make_float2(acc[mf][nt][2], acc[mf][nt][3]);
        }
    }
}

__global__ void op_combine(const float* __restrict__ partial, float* __restrict__ h)
{
    int idx = blockIdx.x * 256 + threadIdx.x;          // 524288
    h[idx] += partial[idx] + partial[idx + 1024 * 512]
            + partial[idx + 2 * 1024 * 512] + partial[idx + 3 * 1024 * 512];
}

// ===========================================================================
// 128x64 core (for patch embed + x_proj, N=64).
// ===========================================================================
__device__ __forceinline__ void mma_core_db(const float* __restrict__ Ab, int lda,
                                            const float* __restrict__ Wb, int ldw,
                                            int kend, float (&acc)[2][4][4])
{
    __shared__ __align__(16) float As[2][128][20];
    __shared__ __align__(16) float Bs[2][64][20];

    const int tid  = threadIdx.x;
    const int warp = tid >> 5, lane = tid & 31;
    const int wy = warp >> 1, wx = warp & 1;
    const int g = lane >> 2, t = lane & 3;

    const int arow = tid >> 1, acol = (tid & 1) * 8;
    const int brow = tid >> 2, bcol = (tid & 3) * 4;

    {
        float4 va0 = *reinterpret_cast<const float4*>(Ab + (size_t)arow * lda + acol);
        float4 va1 = *reinterpret_cast<const float4*>(Ab + (size_t)arow * lda + acol + 4);
        float4 vb  = *reinterpret_cast<const float4*>(Wb + (size_t)brow * ldw + bcol);
        *reinterpret_cast<float4*>(&As[0][arow][acol])     = cvt4(va0);
        *reinterpret_cast<float4*>(&As[0][arow][acol + 4]) = cvt4(va1);
        *reinterpret_cast<float4*>(&Bs[0][brow][bcol])     = cvt4(vb);
    }
    __syncthreads();

    const int niter = kend >> 4;
    for (int it = 0; it < niter; it++) {
        const int cur = it & 1;
        float4 pa0, pa1, pb;
        const bool more = (it + 1 < niter);
        if (more) {
            int k0 = (it + 1) << 4;
            pa0 = *reinterpret_cast<const float4*>(Ab + (size_t)arow * lda + k0 + acol);
            pa1 = *reinterpret_cast<const float4*>(Ab + (size_t)arow * lda + k0 + acol + 4);
            pb  = *reinterpret_cast<const float4*>(Wb + (size_t)brow * ldw + k0 + bcol);
        }

#pragma unroll
        for (int k8 = 0; k8 < 16; k8 += 8) {
            uint32_t a[2][4], b[4][2];
#pragma unroll
            for (int mf = 0; mf < 2; mf++) {
                const int ar = wy * 32 + mf * 16 + g;
                a[mf][0] = __float_as_uint(As[cur][ar][k8 + t]);
                a[mf][1] = __float_as_uint(As[cur][ar + 8][k8 + t]);
                a[mf][2] = __float_as_uint(As[cur][ar][k8 + t + 4]);
                a[mf][3] = __float_as_uint(As[cur][ar + 8][k8 + t + 4]);
            }
#pragma unroll
            for (int nt = 0; nt < 4; nt++) {
                const int bn = wx * 32 + nt * 8 + g;
                b[nt][0] = __float_as_uint(Bs[cur][bn][k8 + t]);
                b[nt][1] = __float_as_uint(Bs[cur][bn][k8 + t + 4]);
            }
#pragma unroll
            for (int mf = 0; mf < 2; mf++)
#pragma unroll
                for (int nt = 0; nt < 4; nt++)
                    mma_tf32(acc[mf][nt][0], acc[mf][nt][1], acc[mf][nt][2], acc[mf][nt][3],
                             a[mf][0], a[mf][1], a[mf][2], a[mf][3],
                             b[nt][0], b[nt][1]);
        }

        if (more) {
            const int nxt = cur ^ 1;
            *reinterpret_cast<float4*>(&As[nxt][arow][acol])     = cvt4(pa0);
            *reinterpret_cast<float4*>(&As[nxt][arow][acol + 4]) = cvt4(pa1);
            *reinterpret_cast<float4*>(&Bs[nxt][brow][bcol])     = cvt4(pb);
            __syncthreads();
        }
    }
}

#define MMA_PROLOGUE                                              \
    const int warp = threadIdx.x >> 5, lane = threadIdx.x & 31;   \
    const int wy = warp >> 1, wx = warp & 1;                      \
    const int g = lane >> 2, t = lane & 3;                        \
    float acc[2][4][4];                                           \
    _Pragma("unroll")                                             \
    for (int i = 0; i < 2; i++)                                   \
        _Pragma("unroll")                                         \
        for (int j = 0; j < 4; j++)                               \
            _Pragma("unroll")                                     \
            for (int q = 0; q < 4; q++) acc[i][j][q] = 0.f;

// patch embed GEMM (with bias): grid (8, 8).
__global__ void __launch_bounds__(256)
gemm32_plain(const float* __restrict__ A, int lda,
             const float* __restrict__ W, int ldw,
             float* __restrict__ C, int ldc, int K,
             const float* __restrict__ bias)
{
    const int rowBase = blockIdx.y * 128;
    const int colBase = blockIdx.x * 64;
    MMA_PROLOGUE
    mma_core_db(A + (size_t)rowBase * lda, lda, W + (size_t)colBase * ldw, ldw, K, acc);

#pragma unroll
    for (int mf = 0; mf < 2; mf++) {
        const int r0 = rowBase + wy * 32 + mf * 16 + g;
#pragma unroll
        for (int nt = 0; nt < 4; nt++) {
            int cb = colBase + wx * 32 + nt * 8 + 2 * t;
            float v0 = acc[mf][nt][0], v1 = acc[mf][nt][1];
            float v2 = acc[mf][nt][2], v3 = acc[mf][nt][3];
            if (bias) { v0 += bias[cb]; v1 += bias[cb + 1]; v2 += bias[cb]; v3 += bias[cb + 1]; }
            *reinterpret_cast<float2*>(&C[(size_t)r0 * ldc + cb])       = make_float2(v0, v1);
            *reinterpret_cast<float2*>(&C[(size_t)(r0 + 8) * ldc + cb]) = make_float2(v2, v3);
        }
    }
}

// x_proj partial, split-K(16) + dir-batched: grid (16 kc, 8 m, 2 dir) = 256.
__global__ void __launch_bounds__(256)
gemm32_xproj_part(const float* __restrict__ ubase,
                  const float* __restrict__ W0, const float* __restrict__ W1,
                  float* __restrict__ partial)
{
    const int kc  = blockIdx.x;
    const int dir = blockIdx.z;
    const float* A = ubase + (size_t)dir * (1024 * 1024) + kc * 64;
    const float* W = (dir ? W1 : W0) + kc * 64;
    const int rowBase = blockIdx.y * 128;
    MMA_PROLOGUE
    mma_core_db(A + (size_t)rowBase * 1024, 1024, W, 1024, 64, acc);

    float* out = partial + ((size_t)(dir * 16 + kc)) * (1024 * 64);
#pragma unroll
    for (int mf = 0; mf < 2; mf++) {
        const int r0 = rowBase + wy * 32 + mf * 16 + g;
#pragma unroll
        for (int nt = 0; nt < 4; nt++) {
            int cb = wx * 32 + nt * 8 + 2 * t;
            *reinterpret_cast<float2*>(&out[(size_t)r0 * 64 + cb])       = make_float2(acc[mf][nt][0], acc[mf][nt][1]);
            *reinterpret_cast<float2*>(&out[(size_t)(r0 + 8) * 64 + cb]) = make_float2(acc[mf][nt][2], acc[mf][nt][3]);
        }
    }
}

__global__ void xproj_reduce(const float* __restrict__ partial, float* __restrict__ xdbase)
{
    int idx = blockIdx.x * 256 + threadIdx.x;          // 2*65536
    int dir = idx >> 16;
    int rem = idx & 65535;
    float s = 0.f;
#pragma unroll
    for (int kc = 0; kc < 16; kc++)
        s += partial[((size_t)(dir * 16 + kc) << 16) + rem];
    xdbase[((size_t)dir << 16) + rem] = s;
}

// ---------------------------------------------------------------------------
// im2col for patch embed
// ---------------------------------------------------------------------------
__global__ void im2col_kernel(const float* __restrict__ x, float* __restrict__ out)
{
    int idx = blockIdx.x * 256 + threadIdx.x;          // 1024*256
    int k = idx & 255;  int m = idx >> 8;
    int q = k & 15;     int p = k >> 4;
    int w = m & 31;     int hh = (m >> 5) & 7;  int b = m >> 8;
    out[idx] = x[((size_t)(b * 128 + hh * 16 + p) << 9) + w * 16 + q];
}

// ---------------------------------------------------------------------------
// LayerNorm: one warp per row of 512.
// ---------------------------------------------------------------------------
__global__ void ln_kernel(const float* __restrict__ x, float* __restrict__ y,
                          const float* __restrict__ w, const float* __restrict__ bsh,
                          int rows)
{
    int warp = (blockIdx.x * blockDim.x + threadIdx.x) >> 5;
    int lane = threadIdx.x & 31;
    if (warp >= rows) return;
    const float* xr = x + (size_t)warp * 512;
    float v[16]; float s = 0.f, s2 = 0.f;
#pragma unroll
    for (int i = 0; i < 16; i++) {
        float tv = xr[lane + i * 32];
        v[i] = tv; s += tv; s2 += tv * tv;
    }
#pragma unroll
    for (int o = 16; o; o >>= 1) {
        s  += __shfl_xor_sync(0xffffffffu, s, o);
        s2 += __shfl_xor_sync(0xffffffffu, s2, o);
    }
    float m   = s * (1.f / 512.f);
    float var = s2 * (1.f / 512.f) - m * m;
    float inv = rsqrtf(var + 1e-5f);
    float* yr = y + (size_t)warp * 512;
#pragma unroll
    for (int i = 0; i < 16; i++) {
        int c = lane + i * 32;
        yr[c] = (v[i] - m) * inv * w[c] + bsh[c];
    }
}

// ---------------------------------------------------------------------------
// Depthwise causal conv (K=4) + SiLU; dir=1 operates on time-flipped sequence.
// ---------------------------------------------------------------------------
__global__ void conv_silu_kernel(const float* __restrict__ xz,
                                 const float* __restrict__ cwf, const float* __restrict__ cbf,
                                 const float* __restrict__ cwb, const float* __restrict__ cbb,
                                 float* __restrict__ u0, float* __restrict__ u1)
{
    int idx = blockIdx.x * 256 + threadIdx.x;          // 0 .. 1M-1
    int dir = blockIdx.y;
    int d = idx & 1023;
    int r = idx >> 10;
    int l = r & 255;  int b = r >> 8;
    const float* cw = dir ? cwb : cwf;
    const float* cb = dir ? cbb : cbf;
    float acc = cb[d];
#pragma unroll
    for (int k = 0; k < 4; k++) {
        int p = l - 3 + k;
        if (p >= 0) {
            int torig = dir ? (255 - p) : p;
            acc += xz[((size_t)(b * 256 + torig) << 11) + d] * cw[d * 4 + k];
        }
    }
    float sg = 1.f / (1.f + __expf(-acc));
    (dir ? u1 : u0)[idx] = acc * sg;
}

// ---------------------------------------------------------------------------
// Selective scan with FUSED dt_proj+softplus. Split-state: 2 threads per
// channel x 8 states. grid (16, 4, 2), 128 threads.
// ---------------------------------------------------------------------------
__global__ void scan_kernel(const float* __restrict__ ubase,
                            const float* __restrict__ xdbase,
                            const float* __restrict__ dtw0, const float* __restrict__ dtw1,
                            const float* __restrict__ dtb0, const float* __restrict__ dtb1,
                            const float* __restrict__ Af,  const float* __restrict__ Ab,
                            const float* __restrict__ Dfp, const float* __restrict__ Dbp,
                            float* __restrict__ ybase)
{
    const int tid  = threadIdx.x;
    const int half = tid & 1;
    const int d    = blockIdx.x * 64 + (tid >> 1);
    const int b    = blockIdx.y;
    const int dir  = blockIdx.z;
    const float* u  = ubase  + (size_t)dir * (1024 * 1024);
    const float* xd = xdbase + (size_t)dir * (1024 * XDW);
    const float* dtw = (dir ? dtw1 : dtw0) + d * 32 + half * 16;
    const float  dtb = (dir ? dtb1 : dtb0)[d];
    const float* Al = dir ? Ab  : Af;
    const float* Dp = dir ? Dbp : Dfp;
    float* y = ybase + (size_t)dir * (1024 * 1024);

    float w[16];
#pragma unroll
    for (int i = 0; i < 16; i++) w[i] = dtw[i];
    float A[8];
#pragma unroll
    for (int s = 0; s < 8; s++) A[s] = -__expf(Al[d * NS + half * 8 + s]);
    float Dv = Dp[d];
    float st[8];
#pragma unroll
    for (int s = 0; s < 8; s++) st[s] = 0.f;

    __shared__ float sXD[256];
    const size_t rowbase = (size_t)b * 256;
    for (int t0 = 0; t0 < 256; t0 += 4) {
        sXD[tid]       = xd[(rowbase + t0 + (tid >> 6)) * XDW + (tid & 63)];
        sXD[tid + 128] = xd[(rowbase + t0 + 2 + (tid >> 6)) * XDW + (tid & 63)];
        __syncthreads();
        float uv[4];
#pragma unroll
        for (int q = 0; q < 4; q++)
            uv[q] = u[(rowbase + t0 + q) * 1024 + d];
#pragma unroll
        for (int q = 0; q < 4; q++) {
            const float* xr = sXD + q * 64;
            float dot = 0.f;
#pragma unroll
            for (int i = 0; i < 16; i++) dot = fmaf(w[i], xr[half * 16 + i], dot);
            dot += __shfl_xor_sync(0xffffffffu, dot, 1);
            float dtv = dot + dtb;
            dtv = (dtv > 20.f) ? dtv : log1pf(__expf(dtv));

            const float* bc = xr + 32 + half * 8;
            float du = dtv * uv[q];
            float yv = 0.f;
#pragma unroll
            for (int s = 0; s < 8; s++) {
                float dA = __expf(dtv * A[s]);
                st[s] = st[s] * dA + du * bc[s];
                yv   += st[s] * bc[16 + s];
            }
            yv += __shfl_xor_sync(0xffffffffu, yv, 1);
            if (half == 0)
                y[(rowbase + t0 + q) * 1024 + d] = yv + uv[q] * Dv;
        }
        __syncthreads();
    }
}

// ---------------------------------------------------------------------------
// Combine: yg = (y_f + flip_L(y_b)) * silu(z)
// ---------------------------------------------------------------------------
__global__ void gate_kernel(const float* __restrict__ ybase,
                            const float* __restrict__ xz, float* __restrict__ yg)
{
    int idx = blockIdx.x * 256 + threadIdx.x;          // 1M
    int d = idx & 1023;  int r = idx >> 10;
    int l = r & 255;     int b = r >> 8;
    float z  = xz[((size_t)r << 11) + 1024 + d];
    float yv = ybase[idx] +
               ybase[1024 * 1024 + (((size_t)(b * 256) + (255 - l)) << 10) + d];
    yg[idx] = yv * (z / (1.f + __expf(-z)));
}

// ---------------------------------------------------------------------------
// Mean pool over L.
// ---------------------------------------------------------------------------
__global__ void pool_kernel(const float* __restrict__ xn, float* __restrict__ feat)
{
    int idx = blockIdx.x * 256 + threadIdx.x;          // 4*512
    if (idx >= 4 * 512) return;
    int b = idx >> 9, d = idx & 511;
    float s = 0.f;
    for (int l = 0; l < 256; l++) s += xn[((size_t)(b * 256 + l) << 9) + d];
    feat[idx] = s * (1.f / 256.f);
}

// ---------------------------------------------------------------------------
// Small FC: one warp per output element.
// ---------------------------------------------------------------------------
__global__ void fc_kernel(const float* __restrict__ in, const float* __restrict__ Wt,
                          const float* __restrict__ bias, float* __restrict__ out,
                          int Brows, int N, int K, int relu)
{
    int warp = (blockIdx.x * blockDim.x + threadIdx.x) >> 5;
    int lane = threadIdx.x & 31;
    if (warp >= Brows * N) return;
    int b = warp / N, j = warp % N;
    const float* ir = in + (size_t)b * K;
    const float* wr = Wt + (size_t)j * K;
    float s = 0.f;
    for (int k = lane; k < K; k += 32) s += ir[k] * wr[k];
#pragma unroll
    for (int o = 16; o; o >>= 1) s += __shfl_xor_sync(0xffffffffu, s, o);
    if (lane == 0) {
        float v = s + bias[j];
        if (relu) v = fmaxf(v, 0.f);
        out[warp] = v;
    }
}

// ---------------------------------------------------------------------------
// kernel_launch
// ---------------------------------------------------------------------------
extern "C" void kernel_launch(void* const* d_in, const int* in_sizes, int n_in,
                              void* d_out, int out_size)
{
    float* sc = nullptr;
    cudaGetSymbolAddress((void**)&sc, g_scratch);

    auto F = [&](int i) { return (const float*)d_in[i]; };
    const float *x = F(0), *patch_w = F(1), *patch_b = F(2), *in_proj_w = F(3);
    const float *conv_w_f, *conv_b_f, *conv_w_b, *conv_b_b;
    const float *xproj_w_f, *xproj_w_b, *dtproj_w_f, *dtproj_b_f, *dtproj_w_b, *dtproj_b_b;
    const float *A_log_f, *A_log_b, *D_f, *D_b;

    if (in_sizes[6] == 16384) {
        conv_w_f = F(4);  conv_b_f = F(5);  conv_w_b = F(6);  conv_b_b = F(7);
        xproj_w_f = F(8); xproj_w_b = F(9);
        dtproj_w_f = F(10); dtproj_b_f = F(11); dtproj_w_b = F(12); dtproj_b_b = F(13);
        A_log_f = F(14); A_log_b = F(15); D_f = F(16); D_b = F(17);
    } else {
        conv_w_f = F(4);  conv_b_f = F(5);  xproj_w_f = F(6); dtproj_w_f = F(7);
        dtproj_b_f = F(8); A_log_f = F(9);  D_f = F(10);
        conv_w_b = F(11); conv_b_b = F(12); xproj_w_b = F(13); dtproj_w_b = F(14);
        dtproj_b_b = F(15); A_log_b = F(16); D_b = F(17);
    }
    const float *out_proj_w = F(18), *norm_w = F(19), *norm_b = F(20);
    const float *normf_w = F(21), *normf_b = F(22), *ln_w = F(23), *ln_b = F(24);
    const float *fc1_w = F(25), *fc1_b = F(26), *fc2_w = F(27), *fc2_b = F(28);

    float* h_p    = sc + OFF_H;
    float* xn_p   = sc + OFF_XN;
    float* xz_p   = sc + OFF_XZ;
    float* u_p    = sc + OFF_U0;
    float* xd_p   = sc + OFF_XD0;
    float* y_p    = sc + OFF_Y0;
    float* yg_p   = sc + OFF_YG;
    float* im_p   = sc + OFF_IM;
    float* xpp_p  = sc + OFF_XPP;
    float* opp_p  = sc + OFF_OPP;
    float* feat_p = sc + OFF_FEAT;
    float* c_p    = sc + OFF_C;
    float* f1_p   = sc + OFF_F1;

    // ---- patch embed --------------------------------------------------------
    im2col_kernel<<<1024, 256>>>(x, im_p);
    gemm32_plain<<<dim3(8, 8), 256>>>(im_p, 256, patch_w, 256, h_p, 512, 256, patch_b);

    for (int i = 0; i < 4; i++) {
        ln_kernel<<<128, 256>>>(h_p, xn_p, norm_w + i * 512, norm_b + i * 512, 1024);

        // in_proj: 1024 x 2048 x 512 (64x128 tiles, grid 16x16 = 256 blocks)
        gemm64_inproj<<<dim3(16, 16), 256>>>(
            xn_p, in_proj_w + (size_t)i * 2048 * 512, xz_p);

        conv_silu_kernel<<<dim3(4096, 2), 256>>>(
            xz_p,
            conv_w_f + i * 4096, conv_b_f + i * 1024,
            conv_w_b + i * 4096, conv_b_b + i * 1024,
            u_p, u_p + 1024 * 1024);

        // x_proj: split-K(16), dir-batched, 256 blocks
        gemm32_xproj_part<<<dim3(16, 8, 2), 256>>>(
            u_p, xproj_w_f + (size_t)i * XDW * 1024, xproj_w_b + (size_t)i * XDW * 1024,
            xpp_p);
        xproj_reduce<<<512, 256>>>(xpp_p, xd_p);

        scan_kernel<<<dim3(16, 4, 2), 128>>>(
            u_p, xd_p,
            dtproj_w_f + (size_t)i * 1024 * 32, dtproj_w_b + (size_t)i * 1024 * 32,
            dtproj_b_f + i * 1024, dtproj_b_b + i * 1024,
            A_log_f + i * 16384, A_log_b + i * 16384,
            D_f + i * 1024, D_b + i * 1024,
            y_p);

        gate_kernel<<<4096, 256>>>(y_p, xz_p, yg_p);

        // out_proj: 64x128 tiles, split-K(4), grid (4,16,4) = 256 blocks
        gemm64_op_part<<<dim3(4, 16, 4), 256>>>(
            yg_p, out_proj_w + (size_t)i * 512 * 1024, opp_p);
        op_combine<<<2048, 256>>>(opp_p, h_p);
    }

    // ---- head ---------------------------------------------------------------
    ln_kernel<<<128, 256>>>(h_p, xn_p, normf_w, normf_b, 1024);
    pool_kernel<<<8, 256>>>(xn_p, feat_p);
    ln_kernel<<<1, 256>>>(feat_p, c_p, ln_w, ln_b, 4);
    fc_kernel<<<256, 256>>>(c_p, fc1_w, fc1_b, f1_p, 4, 512, 512, 1);
    fc_kernel<<<5, 256>>>(f1_p, fc2_w, fc2_b, (float*)d_out, 4, 10, 512, 0);
}

// round 14
// speedup vs baseline: 1.0529x; 1.0529x over previous
#include <cuda_runtime.h>
#include <cstdint>
#include <cstddef>

// ---------------------------------------------------------------------------
// AudioMamba forward on GB300 — R10 resubmit (5th attempt): R7 base +
// in_proj split-K2 (2 CTAs/SM, combine fused into conv/gate) +
// op_combine+LN fused.
// ---------------------------------------------------------------------------

constexpr int NS = 16;
constexpr int XDW = 64;
constexpr size_t XZP_STRIDE = (size_t)1024 * 2048;   // between in_proj partials

// ---- scratch --------------------------------------------------------------
constexpr size_t OFF_H    = 0;
constexpr size_t OFF_XN   = OFF_H    + 1024 * 512;
constexpr size_t OFF_XZP  = OFF_XN   + 1024 * 512;        // 2 x 1024 x 2048
constexpr size_t OFF_U0   = OFF_XZP  + 2 * 1024 * 2048;
constexpr size_t OFF_XD0  = OFF_U0   + 2 * 1024 * 1024;
constexpr size_t OFF_Y0   = OFF_XD0  + 2 * 1024 * XDW;
constexpr size_t OFF_YG   = OFF_Y0   + 2 * 1024 * 1024;
constexpr size_t OFF_IM   = OFF_YG   + 1024 * 1024;
constexpr size_t OFF_XPP  = OFF_IM   + 1024 * 256;        // 16 x 1024 x 64
constexpr size_t OFF_OPP  = OFF_XPP  + 16 * 1024 * 64;    // 4 x 1024 x 512
constexpr size_t OFF_FEAT = OFF_OPP  + 4 * 1024 * 512;
constexpr size_t OFF_C    = OFF_FEAT + 4 * 512;
constexpr size_t OFF_F1   = OFF_C    + 4 * 512;
constexpr size_t SCRATCH_FLOATS = OFF_F1 + 4 * 512;

__device__ __align__(16) float g_scratch[SCRATCH_FLOATS];

// ---------------------------------------------------------------------------
// tf32 helpers
// ---------------------------------------------------------------------------
__device__ __forceinline__ float f2tf32(float f) {
    uint32_t u;
    asm("cvt.rna.tf32.f32 %0, %1;" : "=r"(u) : "f"(f));
    return __uint_as_float(u);
}
__device__ __forceinline__ float4 cvt4(float4 v) {
    return make_float4(f2tf32(v.x), f2tf32(v.y), f2tf32(v.z), f2tf32(v.w));
}

__device__ __forceinline__ void mma_tf32(float& c0, float& c1, float& c2, float& c3,
                                         uint32_t a0, uint32_t a1, uint32_t a2, uint32_t a3,
                                         uint32_t b0, uint32_t b1)
{
    asm volatile(
        "mma.sync.aligned.m16n8k8.row.col.f32.tf32.tf32.f32 "
        "{%0,%1,%2,%3}, {%4,%5,%6,%7}, {%8,%9}, {%0,%1,%2,%3};\n"
        : "+f"(c0), "+f"(c1), "+f"(c2), "+f"(c3)
        : "r"(a0), "r"(a1), "r"(a2), "r"(a3), "r"(b0), "r"(b1));
}

// ===========================================================================
// WIDE core: 128x128 block tile, BK=16, 256 threads, warp tile 32x64 (R7).
// ===========================================================================
__device__ __forceinline__ void mma_core_wide(const float* __restrict__ Ab, int lda,
                                              const float* __restrict__ Wb, int ldw,
                                              int kend, float (&acc)[2][8][4])
{
    __shared__ __align__(16) float As[2][128][20];
    __shared__ __align__(16) float Bs[2][128][20];

    const int tid  = threadIdx.x;
    const int warp = tid >> 5, lane = tid & 31;
    const int wy = warp >> 1, wx = warp & 1;
    const int g = lane >> 2, t = lane & 3;

    const int row = tid >> 1, col = (tid & 1) * 8;

    {
        float4 a0 = *reinterpret_cast<const float4*>(Ab + (size_t)row * lda + col);
        float4 a1 = *reinterpret_cast<const float4*>(Ab + (size_t)row * lda + col + 4);
        float4 b0 = *reinterpret_cast<const float4*>(Wb + (size_t)row * ldw + col);
        float4 b1 = *reinterpret_cast<const float4*>(Wb + (size_t)row * ldw + col + 4);
        *reinterpret_cast<float4*>(&As[0][row][col])     = cvt4(a0);
        *reinterpret_cast<float4*>(&As[0][row][col + 4]) = cvt4(a1);
        *reinterpret_cast<float4*>(&Bs[0][row][col])     = cvt4(b0);
        *reinterpret_cast<float4*>(&Bs[0][row][col + 4]) = cvt4(b1);
    }
    __syncthreads();

    const int niter = kend >> 4;
    for (int it = 0; it < niter; it++) {
        const int cur = it & 1;
        float4 pa0, pa1, pb0, pb1;
        const bool more = (it + 1 < niter);
        if (more) {
            int k0 = (it + 1) << 4;
            pa0 = *reinterpret_cast<const float4*>(Ab + (size_t)row * lda + k0 + col);
            pa1 = *reinterpret_cast<const float4*>(Ab + (size_t)row * lda + k0 + col + 4);
            pb0 = *reinterpret_cast<const float4*>(Wb + (size_t)row * ldw + k0 + col);
            pb1 = *reinterpret_cast<const float4*>(Wb + (size_t)row * ldw + k0 + col + 4);
        }

#pragma unroll
        for (int k8 = 0; k8 < 16; k8 += 8) {
            uint32_t a[2][4];
#pragma unroll
            for (int mf = 0; mf < 2; mf++) {
                const int ar = wy * 32 + mf * 16 + g;
                a[mf][0] = __float_as_uint(As[cur][ar][k8 + t]);
                a[mf][1] = __float_as_uint(As[cur][ar + 8][k8 + t]);
                a[mf][2] = __float_as_uint(As[cur][ar][k8 + t + 4]);
                a[mf][3] = __float_as_uint(As[cur][ar + 8][k8 + t + 4]);
            }
#pragma unroll
            for (int nt = 0; nt < 8; nt++) {
                const int bn = wx * 64 + nt * 8 + g;
                uint32_t b0 = __float_as_uint(Bs[cur][bn][k8 + t]);
                uint32_t b1 = __float_as_uint(Bs[cur][bn][k8 + t + 4]);
#pragma unroll
                for (int mf = 0; mf < 2; mf++)
                    mma_tf32(acc[mf][nt][0], acc[mf][nt][1], acc[mf][nt][2], acc[mf][nt][3],
                             a[mf][0], a[mf][1], a[mf][2], a[mf][3], b0, b1);
            }
        }

        if (more) {
            const int nxt = cur ^ 1;
            *reinterpret_cast<float4*>(&As[nxt][row][col])     = cvt4(pa0);
            *reinterpret_cast<float4*>(&As[nxt][row][col + 4]) = cvt4(pa1);
            *reinterpret_cast<float4*>(&Bs[nxt][row][col])     = cvt4(pb0);
            *reinterpret_cast<float4*>(&Bs[nxt][row][col + 4]) = cvt4(pb1);
            __syncthreads();
        }
    }
}

#define WIDE_PROLOGUE                                             \
    const int warp = threadIdx.x >> 5, lane = threadIdx.x & 31;   \
    const int wy = warp >> 1, wx = warp & 1;                      \
    const int g = lane >> 2, t = lane & 3;                        \
    float acc[2][8][4];                                           \
    _Pragma("unroll")                                             \
    for (int i = 0; i < 2; i++)                                   \
        _Pragma("unroll")                                         \
        for (int j = 0; j < 8; j++)                               \
            _Pragma("unroll")                                     \
            for (int q = 0; q < 4; q++) acc[i][j][q] = 0.f;

#define WIDE_EPILOGUE(Cptr, ldc, rowBase, colBase)                \
    _Pragma("unroll")                                             \
    for (int mf = 0; mf < 2; mf++) {                              \
        const int r0 = (rowBase) + wy * 32 + mf * 16 + g;         \
        _Pragma("unroll")                                         \
        for (int nt = 0; nt < 8; nt++) {                          \
            int cb = (colBase) + wx * 64 + nt * 8 + 2 * t;        \
            *reinterpret_cast<float2*>(&(Cptr)[(size_t)r0 * (ldc) + cb])       = make_float2(acc[mf][nt][0], acc[mf][nt][1]); \
            *reinterpret_cast<float2*>(&(Cptr)[(size_t)(r0 + 8) * (ldc) + cb]) = make_float2(acc[mf][nt][2], acc[mf][nt][3]); \
        }                                                         \
    }

// in_proj split-K(2): grid (16 n, 8 m, 2 kc) = 256 blocks, K-chunk 256.
// Writes partials xzp[kc][1024][2048]; consumers add the two partials.
__global__ void __launch_bounds__(256, 2)
gemm32_inproj_sk(const float* __restrict__ A,       // 1024 x 512
                 const float* __restrict__ W,       // 2048 x 512
                 float* __restrict__ xzp)           // [2][1024][2048]
{
    const int kc = blockIdx.z;
    const int rowBase = blockIdx.y * 128;
    const int colBase = blockIdx.x * 128;
    WIDE_PROLOGUE
    mma_core_wide(A + (size_t)rowBase * 512 + kc * 256, 512,
                  W + (size_t)colBase * 512 + kc * 256, 512, 256, acc);
    float* out = xzp + (size_t)kc * XZP_STRIDE;
    WIDE_EPILOGUE(out, 2048, rowBase, colBase)
}

// out_proj partial, split-K(4): grid (4 n, 8 m, 4 kc). K-chunk 256. (R7)
__global__ void __launch_bounds__(256)
gemm32_op_wide(const float* __restrict__ yg, const float* __restrict__ Wop,
               float* __restrict__ partial)
{
    const int kc = blockIdx.z;
    const float* A = yg + kc * 256;
    const float* W = Wop + kc * 256;
    const int rowBase = blockIdx.y * 128;
    const int colBase = blockIdx.x * 128;
    WIDE_PROLOGUE
    mma_core_wide(A + (size_t)rowBase * 1024, 1024, W + (size_t)colBase * 1024, 1024, 256, acc);

    float* out = partial + (size_t)kc * (1024 * 512);
    WIDE_EPILOGUE(out, 512, rowBase, colBase)
}

// ---------------------------------------------------------------------------
// Fused residual combine + LayerNorm: h += sum partials; xn = LN(h)*gw+gb.
// One warp per row; grid 128 x 256.
// ---------------------------------------------------------------------------
__global__ void combine_ln_kernel(const float* __restrict__ partial,
                                  float* __restrict__ h,
                                  const float* __restrict__ gw, const float* __restrict__ gb,
                                  float* __restrict__ xn)
{
    int rowid = (blockIdx.x * 256 + threadIdx.x) >> 5;
    int lane  = threadIdx.x & 31;
    float* hr = h + (size_t)rowid * 512;
    const float* p = partial + (size_t)rowid * 512;
    float v[16]; float s = 0.f, s2 = 0.f;
#pragma unroll
    for (int i = 0; i < 16; i++) {
        int c = lane + i * 32;
        float tv = hr[c] + p[c] + p[c + 1024 * 512]
                 + p[c + 2 * 1024 * 512] + p[c + 3 * 1024 * 512];
        hr[c] = tv;
        v[i] = tv; s += tv; s2 += tv * tv;
    }
#pragma unroll
    for (int o = 16; o; o >>= 1) {
        s  += __shfl_xor_sync(0xffffffffu, s, o);
        s2 += __shfl_xor_sync(0xffffffffu, s2, o);
    }
    float m   = s * (1.f / 512.f);
    float var = s2 * (1.f / 512.f) - m * m;
    float inv = rsqrtf(var + 1e-5f);
    float* yr = xn + (size_t)rowid * 512;
#pragma unroll
    for (int i = 0; i < 16; i++) {
        int c = lane + i * 32;
        yr[c] = (v[i] - m) * inv * gw[c] + gb[c];
    }
}

// ===========================================================================
// 128x64 core (patch embed + x_proj). (R7)
// ===========================================================================
__device__ __forceinline__ void mma_core_db(const float* __restrict__ Ab, int lda,
                                            const float* __restrict__ Wb, int ldw,
                                            int kend, float (&acc)[2][4][4])
{
    __shared__ __align__(16) float As[2][128][20];
    __shared__ __align__(16) float Bs[2][64][20];

    const int tid  = threadIdx.x;
    const int warp = tid >> 5, lane = tid & 31;
    const int wy = warp >> 1, wx = warp & 1;
    const int g = lane >> 2, t = lane & 3;

    const int arow = tid >> 1, acol = (tid & 1) * 8;
    const int brow = tid >> 2, bcol = (tid & 3) * 4;

    {
        float4 va0 = *reinterpret_cast<const float4*>(Ab + (size_t)arow * lda + acol);
        float4 va1 = *reinterpret_cast<const float4*>(Ab + (size_t)arow * lda + acol + 4);
        float4 vb  = *reinterpret_cast<const float4*>(Wb + (size_t)brow * ldw + bcol);
        *reinterpret_cast<float4*>(&As[0][arow][acol])     = cvt4(va0);
        *reinterpret_cast<float4*>(&As[0][arow][acol + 4]) = cvt4(va1);
        *reinterpret_cast<float4*>(&Bs[0][brow][bcol])     = cvt4(vb);
    }
    __syncthreads();

    const int niter = kend >> 4;
    for (int it = 0; it < niter; it++) {
        const int cur = it & 1;
        float4 pa0, pa1, pb;
        const bool more = (it + 1 < niter);
        if (more) {
            int k0 = (it + 1) << 4;
            pa0 = *reinterpret_cast<const float4*>(Ab + (size_t)arow * lda + k0 + acol);
            pa1 = *reinterpret_cast<const float4*>(Ab + (size_t)arow * lda + k0 + acol + 4);
            pb  = *reinterpret_cast<const float4*>(Wb + (size_t)brow * ldw + k0 + bcol);
        }

#pragma unroll
        for (int k8 = 0; k8 < 16; k8 += 8) {
            uint32_t a[2][4], b[4][2];
#pragma unroll
            for (int mf = 0; mf < 2; mf++) {
                const int ar = wy * 32 + mf * 16 + g;
                a[mf][0] = __float_as_uint(As[cur][ar][k8 + t]);
                a[mf][1] = __float_as_uint(As[cur][ar + 8][k8 + t]);
                a[mf][2] = __float_as_uint(As[cur][ar][k8 + t + 4]);
                a[mf][3] = __float_as_uint(As[cur][ar + 8][k8 + t + 4]);
            }
#pragma unroll
            for (int nt = 0; nt < 4; nt++) {
                const int bn = wx * 32 + nt * 8 + g;
                b[nt][0] = __float_as_uint(Bs[cur][bn][k8 + t]);
                b[nt][1] = __float_as_uint(Bs[cur][bn][k8 + t + 4]);
            }
#pragma unroll
            for (int mf = 0; mf < 2; mf++)
#pragma unroll
                for (int nt = 0; nt < 4; nt++)
                    mma_tf32(acc[mf][nt][0], acc[mf][nt][1], acc[mf][nt][2], acc[mf][nt][3],
                             a[mf][0], a[mf][1], a[mf][2], a[mf][3],
                             b[nt][0], b[nt][1]);
        }

        if (more) {
            const int nxt = cur ^ 1;
            *reinterpret_cast<float4*>(&As[nxt][arow][acol])     = cvt4(pa0);
            *reinterpret_cast<float4*>(&As[nxt][arow][acol + 4]) = cvt4(pa1);
            *reinterpret_cast<float4*>(&Bs[nxt][brow][bcol])     = cvt4(pb);
            __syncthreads();
        }
    }
}

#define MMA_PROLOGUE                                              \
    const int warp = threadIdx.x >> 5, lane = threadIdx.x & 31;   \
    const int wy = warp >> 1, wx = warp & 1;                      \
    const int g = lane >> 2, t = lane & 3;                        \
    float acc[2][4][4];                                           \
    _Pragma("unroll")                                             \
    for (int i = 0; i < 2; i++)                                   \
        _Pragma("unroll")                                         \
        for (int j = 0; j < 4; j++)                               \
            _Pragma("unroll")                                     \
            for (int q = 0; q < 4; q++) acc[i][j][q] = 0.f;

// patch embed GEMM (with bias): grid (8, 8).
__global__ void __launch_bounds__(256)
gemm32_plain(const float* __restrict__ A, int lda,
             const float* __restrict__ W, int ldw,
             float* __restrict__ C, int ldc, int K,
             const float* __restrict__ bias)
{
    const int rowBase = blockIdx.y * 128;
    const int colBase = blockIdx.x * 64;
    MMA_PROLOGUE
    mma_core_db(A + (size_t)rowBase * lda, lda, W + (size_t)colBase * ldw, ldw, K, acc);

#pragma unroll
    for (int mf = 0; mf < 2; mf++) {
        const int r0 = rowBase + wy * 32 + mf * 16 + g;
#pragma unroll
        for (int nt = 0; nt < 4; nt++) {
            int cb = colBase + wx * 32 + nt * 8 + 2 * t;
            float v0 = acc[mf][nt][0], v1 = acc[mf][nt][1];
            float v2 = acc[mf][nt][2], v3 = acc[mf][nt][3];
            if (bias) { v0 += bias[cb]; v1 += bias[cb + 1]; v2 += bias[cb]; v3 += bias[cb + 1]; }
            *reinterpret_cast<float2*>(&C[(size_t)r0 * ldc + cb])       = make_float2(v0, v1);
            *reinterpret_cast<float2*>(&C[(size_t)(r0 + 8) * ldc + cb]) = make_float2(v2, v3);
        }
    }
}

// x_proj partial, split-K(8) + dir-batched: grid (8 kc, 8 m, 2 dir). (R7)
__global__ void __launch_bounds__(256)
gemm32_xproj_part(const float* __restrict__ ubase,
                  const float* __restrict__ W0, const float* __restrict__ W1,
                  float* __restrict__ partial)
{
    const int kc  = blockIdx.x;
    const int dir = blockIdx.z;
    const float* A = ubase + (size_t)dir * (1024 * 1024) + kc * 128;
    const float* W = (dir ? W1 : W0) + kc * 128;
    const int rowBase = blockIdx.y * 128;
    MMA_PROLOGUE
    mma_core_db(A + (size_t)rowBase * 1024, 1024, W, 1024, 128, acc);

    float* out = partial + ((size_t)(dir * 8 + kc)) * (1024 * 64);
#pragma unroll
    for (int mf = 0; mf < 2; mf++) {
        const int r0 = rowBase + wy * 32 + mf * 16 + g;
#pragma unroll
        for (int nt = 0; nt < 4; nt++) {
            int cb = wx * 32 + nt * 8 + 2 * t;
            *reinterpret_cast<float2*>(&out[(size_t)r0 * 64 + cb])       = make_float2(acc[mf][nt][0], acc[mf][nt][1]);
            *reinterpret_cast<float2*>(&out[(size_t)(r0 + 8) * 64 + cb]) = make_float2(acc[mf][nt][2], acc[mf][nt][3]);
        }
    }
}

__global__ void xproj_reduce(const float* __restrict__ partial, float* __restrict__ xdbase)
{
    int idx = blockIdx.x * 256 + threadIdx.x;          // 2*65536
    int dir = idx >> 16;
    int rem = idx & 65535;
    float s = 0.f;
#pragma unroll
    for (int kc = 0; kc < 8; kc++)
        s += partial[((size_t)(dir * 8 + kc) << 16) + rem];
    xdbase[((size_t)dir << 16) + rem] = s;
}

// ---------------------------------------------------------------------------
// im2col for patch embed
// ---------------------------------------------------------------------------
__global__ void im2col_kernel(const float* __restrict__ x, float* __restrict__ out)
{
    int idx = blockIdx.x * 256 + threadIdx.x;          // 1024*256
    int k = idx & 255;  int m = idx >> 8;
    int q = k & 15;     int p = k >> 4;
    int w = m & 31;     int hh = (m >> 5) & 7;  int b = m >> 8;
    out[idx] = x[((size_t)(b * 128 + hh * 16 + p) << 9) + w * 16 + q];
}

// ---------------------------------------------------------------------------
// LayerNorm (first layer + feat).
// ---------------------------------------------------------------------------
__global__ void ln_kernel(const float* __restrict__ x, float* __restrict__ y,
                          const float* __restrict__ w, const float* __restrict__ bsh,
                          int rows)
{
    int warp = (blockIdx.x * blockDim.x + threadIdx.x) >> 5;
    int lane = threadIdx.x & 31;
    if (warp >= rows) return;
    const float* xr = x + (size_t)warp * 512;
    float v[16]; float s = 0.f, s2 = 0.f;
#pragma unroll
    for (int i = 0; i < 16; i++) {
        float tv = xr[lane + i * 32];
        v[i] = tv; s += tv; s2 += tv * tv;
    }
#pragma unroll
    for (int o = 16; o; o >>= 1) {
        s  += __shfl_xor_sync(0xffffffffu, s, o);
        s2 += __shfl_xor_sync(0xffffffffu, s2, o);
    }
    float m   = s * (1.f / 512.f);
    float var = s2 * (1.f / 512.f) - m * m;
    float inv = rsqrtf(var + 1e-5f);
    float* yr = y + (size_t)warp * 512;
#pragma unroll
    for (int i = 0; i < 16; i++) {
        int c = lane + i * 32;
        yr[c] = (v[i] - m) * inv * w[c] + bsh[c];
    }
}

// ---------------------------------------------------------------------------
// Depthwise causal conv (K=4) + SiLU; reads xz = p0+p1 (in_proj partials).
// ---------------------------------------------------------------------------
__global__ void conv_silu_kernel(const float* __restrict__ xzp,
                                 const float* __restrict__ cwf, const float* __restrict__ cbf,
                                 const float* __restrict__ cwb, const float* __restrict__ cbb,
                                 float* __restrict__ u0, float* __restrict__ u1)
{
    int idx = blockIdx.x * 256 + threadIdx.x;          // 0 .. 1M-1
    int dir = blockIdx.y;
    int d = idx & 1023;
    int r = idx >> 10;
    int l = r & 255;  int b = r >> 8;
    const float* cw = dir ? cwb : cwf;
    const float* cb = dir ? cbb : cbf;
    float acc = cb[d];
#pragma unroll
    for (int k = 0; k < 4; k++) {
        int p = l - 3 + k;
        if (p >= 0) {
            int torig = dir ? (255 - p) : p;
            size_t off = ((size_t)(b * 256 + torig) << 11) + d;
            acc += (xzp[off] + xzp[off + XZP_STRIDE]) * cw[d * 4 + k];
        }
    }
    float sg = 1.f / (1.f + __expf(-acc));
    (dir ? u1 : u0)[idx] = acc * sg;
}

// ---------------------------------------------------------------------------
// Selective scan with FUSED dt_proj+softplus (R7). grid (16, 4, 2), 128 thr.
// ---------------------------------------------------------------------------
__global__ void scan_kernel(const float* __restrict__ ubase,
                            const float* __restrict__ xdbase,
                            const float* __restrict__ dtw0, const float* __restrict__ dtw1,
                            const float* __restrict__ dtb0, const float* __restrict__ dtb1,
                            const float* __restrict__ Af,  const float* __restrict__ Ab,
                            const float* __restrict__ Dfp, const float* __restrict__ Dbp,
                            float* __restrict__ ybase)
{
    const int tid  = threadIdx.x;
    const int half = tid & 1;
    const int d    = blockIdx.x * 64 + (tid >> 1);
    const int b    = blockIdx.y;
    const int dir  = blockIdx.z;
    const float* u  = ubase  + (size_t)dir * (1024 * 1024);
    const float* xd = xdbase + (size_t)dir * (1024 * XDW);
    const float* dtw = (dir ? dtw1 : dtw0) + d * 32 + half * 16;
    const float  dtb = (dir ? dtb1 : dtb0)[d];
    const float* Al = dir ? Ab  : Af;
    const float* Dp = dir ? Dbp : Dfp;
    float* y = ybase + (size_t)dir * (1024 * 1024);

    float w[16];
#pragma unroll
    for (int i = 0; i < 16; i++) w[i] = dtw[i];
    float A[8];
#pragma unroll
    for (int s = 0; s < 8; s++) A[s] = -__expf(Al[d * NS + half * 8 + s]);
    float Dv = Dp[d];
    float st[8];
#pragma unroll
    for (int s = 0; s < 8; s++) st[s] = 0.f;

    __shared__ float sXD[256];
    const size_t rowbase = (size_t)b * 256;
    for (int t0 = 0; t0 < 256; t0 += 4) {
        sXD[tid]       = xd[(rowbase + t0 + (tid >> 6)) * XDW + (tid & 63)];
        sXD[tid + 128] = xd[(rowbase + t0 + 2 + (tid >> 6)) * XDW + (tid & 63)];
        __syncthreads();
        float uv[4];
#pragma unroll
        for (int q = 0; q < 4; q++)
            uv[q] = u[(rowbase + t0 + q) * 1024 + d];
#pragma unroll
        for (int q = 0; q < 4; q++) {
            const float* xr = sXD + q * 64;
            float dot = 0.f;
#pragma unroll
            for (int i = 0; i < 16; i++) dot = fmaf(w[i], xr[half * 16 + i], dot);
            dot += __shfl_xor_sync(0xffffffffu, dot, 1);
            float dtv = dot + dtb;
            dtv = (dtv > 20.f) ? dtv : log1pf(__expf(dtv));

            const float* bc = xr + 32 + half * 8;
            float du = dtv * uv[q];
            float yv = 0.f;
#pragma unroll
            for (int s = 0; s < 8; s++) {
                float dA = __expf(dtv * A[s]);
                st[s] = st[s] * dA + du * bc[s];
                yv   += st[s] * bc[16 + s];
            }
            yv += __shfl_xor_sync(0xffffffffu, yv, 1);
            if (half == 0)
                y[(rowbase + t0 + q) * 1024 + d] = yv + uv[q] * Dv;
        }
        __syncthreads();
    }
}

// ---------------------------------------------------------------------------
// Combine: yg = (y_f + flip_L(y_b)) * silu(z); z = p0+p1 at col 1024+d.
// ---------------------------------------------------------------------------
__global__ void gate_kernel(const float* __restrict__ ybase,
                            const float* __restrict__ xzp, float* __restrict__ yg)
{
    int idx = blockIdx.x * 256 + threadIdx.x;          // 1M
    int d = idx & 1023;  int r = idx >> 10;
    int l = r & 255;     int b = r >> 8;
    size_t zoff = ((size_t)r << 11) + 1024 + d;
    float z  = xzp[zoff] + xzp[zoff + XZP_STRIDE];
    float yv = ybase[idx] +
               ybase[1024 * 1024 + (((size_t)(b * 256) + (255 - l)) << 10) + d];
    yg[idx] = yv * (z / (1.f + __expf(-z)));
}

// ---------------------------------------------------------------------------
// Mean pool over L.
// ---------------------------------------------------------------------------
__global__ void pool_kernel(const float* __restrict__ xn, float* __restrict__ feat)
{
    int idx = blockIdx.x * 256 + threadIdx.x;          // 4*512
    if (idx >= 4 * 512) return;
    int b = idx >> 9, d = idx & 511;
    float s = 0.f;
    for (int l = 0; l < 256; l++) s += xn[((size_t)(b * 256 + l) << 9) + d];
    feat[idx] = s * (1.f / 256.f);
}

// ---------------------------------------------------------------------------
// Small FC: one warp per output element.
// ---------------------------------------------------------------------------
__global__ void fc_kernel(const float* __restrict__ in, const float* __restrict__ Wt,
                          const float* __restrict__ bias, float* __restrict__ out,
                          int Brows, int N, int K, int relu)
{
    int warp = (blockIdx.x * blockDim.x + threadIdx.x) >> 5;
    int lane = threadIdx.x & 31;
    if (warp >= Brows * N) return;
    int b = warp / N, j = warp % N;
    const float* ir = in + (size_t)b * K;
    const float* wr = Wt + (size_t)j * K;
    float s = 0.f;
    for (int k = lane; k < K; k += 32) s += ir[k] * wr[k];
#pragma unroll
    for (int o = 16; o; o >>= 1) s += __shfl_xor_sync(0xffffffffu, s, o);
    if (lane == 0) {
        float v = s + bias[j];
        if (relu) v = fmaxf(v, 0.f);
        out[warp] = v;
    }
}

// ---------------------------------------------------------------------------
// kernel_launch
// ---------------------------------------------------------------------------
extern "C" void kernel_launch(void* const* d_in, const int* in_sizes, int n_in,
                              void* d_out, int out_size)
{
    float* sc = nullptr;
    cudaGetSymbolAddress((void**)&sc, g_scratch);

    auto F = [&](int i) { return (const float*)d_in[i]; };
    const float *x = F(0), *patch_w = F(1), *patch_b = F(2), *in_proj_w = F(3);
    const float *conv_w_f, *conv_b_f, *conv_w_b, *conv_b_b;
    const float *xproj_w_f, *xproj_w_b, *dtproj_w_f, *dtproj_b_f, *dtproj_w_b, *dtproj_b_b;
    const float *A_log_f, *A_log_b, *D_f, *D_b;

    if (in_sizes[6] == 16384) {
        conv_w_f = F(4);  conv_b_f = F(5);  conv_w_b = F(6);  conv_b_b = F(7);
        xproj_w_f = F(8); xproj_w_b = F(9);
        dtproj_w_f = F(10); dtproj_b_f = F(11); dtproj_w_b = F(12); dtproj_b_b = F(13);
        A_log_f = F(14); A_log_b = F(15); D_f = F(16); D_b = F(17);
    } else {
        conv_w_f = F(4);  conv_b_f = F(5);  xproj_w_f = F(6); dtproj_w_f = F(7);
        dtproj_b_f = F(8); A_log_f = F(9);  D_f = F(10);
        conv_w_b = F(11); conv_b_b = F(12); xproj_w_b = F(13); dtproj_w_b = F(14);
        dtproj_b_b = F(15); A_log_b = F(16); D_b = F(17);
    }
    const float *out_proj_w = F(18), *norm_w = F(19), *norm_b = F(20);
    const float *normf_w = F(21), *normf_b = F(22), *ln_w = F(23), *ln_b = F(24);
    const float *fc1_w = F(25), *fc1_b = F(26), *fc2_w = F(27), *fc2_b = F(28);

    float* h_p    = sc + OFF_H;
    float* xn_p   = sc + OFF_XN;
    float* xzp_p  = sc + OFF_XZP;
    float* u_p    = sc + OFF_U0;
    float* xd_p   = sc + OFF_XD0;
    float* y_p    = sc + OFF_Y0;
    float* yg_p   = sc + OFF_YG;
    float* im_p   = sc + OFF_IM;
    float* xpp_p  = sc + OFF_XPP;
    float* opp_p  = sc + OFF_OPP;
    float* feat_p = sc + OFF_FEAT;
    float* c_p    = sc + OFF_C;
    float* f1_p   = sc + OFF_F1;

    // ---- patch embed --------------------------------------------------------
    im2col_kernel<<<1024, 256>>>(x, im_p);
    gemm32_plain<<<dim3(8, 8), 256>>>(im_p, 256, patch_w, 256, h_p, 512, 256, patch_b);
    ln_kernel<<<128, 256>>>(h_p, xn_p, norm_w, norm_b, 1024);   // layer-0 LN

    for (int i = 0; i < 4; i++) {
        // in_proj split-K(2): 256 blocks, partials combined in consumers
        gemm32_inproj_sk<<<dim3(16, 8, 2), 256>>>(
            xn_p, in_proj_w + (size_t)i * 2048 * 512, xzp_p);

        conv_silu_kernel<<<dim3(4096, 2), 256>>>(
            xzp_p,
            conv_w_f + i * 4096, conv_b_f + i * 1024,
            conv_w_b + i * 4096, conv_b_b + i * 1024,
            u_p, u_p + 1024 * 1024);

        gemm32_xproj_part<<<dim3(8, 8, 2), 256>>>(
            u_p, xproj_w_f + (size_t)i * XDW * 1024, xproj_w_b + (size_t)i * XDW * 1024,
            xpp_p);
        xproj_reduce<<<512, 256>>>(xpp_p, xd_p);

        scan_kernel<<<dim3(16, 4, 2), 128>>>(
            u_p, xd_p,
            dtproj_w_f + (size_t)i * 1024 * 32, dtproj_w_b + (size_t)i * 1024 * 32,
            dtproj_b_f + i * 1024, dtproj_b_b + i * 1024,
            A_log_f + i * 16384, A_log_b + i * 16384,
            D_f + i * 1024, D_b + i * 1024,
            y_p);

        gate_kernel<<<4096, 256>>>(y_p, xzp_p, yg_p);

        gemm32_op_wide<<<dim3(4, 8, 4), 256>>>(
            yg_p, out_proj_w + (size_t)i * 512 * 1024, opp_p);

        // residual combine + next LN (normf after last layer)
        const float* ngw = (i < 3) ? norm_w + (i + 1) * 512 : normf_w;
        const float* ngb = (i < 3) ? norm_b + (i + 1) * 512 : normf_b;
        combine_ln_kernel<<<128, 256>>>(opp_p, h_p, ngw, ngb, xn_p);
    }

    // ---- head ---------------------------------------------------------------
    pool_kernel<<<8, 256>>>(xn_p, feat_p);
    ln_kernel<<<1, 256>>>(feat_p, c_p, ln_w, ln_b, 4);
    fc_kernel<<<256, 256>>>(c_p, fc1_w, fc1_b, f1_p, 4, 512, 512, 1);
    fc_kernel<<<5, 256>>>(f1_p, fc2_w, fc2_b, (float*)d_out, 4, 10, 512, 0);
}